// round 15
// baseline (speedup 1.0000x reference)
#include <cuda_runtime.h>
#include <cuda_fp16.h>
#include <cstdint>

// ---------------------------------------------------------------------------
// Problem constants
// ---------------------------------------------------------------------------
#define D_IN    4096
#define H_DIM   256
#define O_DIM   64
#define KC      64        // K-chunk: 64 halves = 128 B rows (SW128)
#define NCHUNK  64        // 4096 / 64
#define TILE_M  128
#define NROWS   32768
#define NTHREADS 512

// ---------------------------------------------------------------------------
// SMEM layout (bytes from dynamic smem base; base is 1024-aligned)
// ---------------------------------------------------------------------------
#define OFF_B1      0                        // 2 x 256 f32
#define OFF_B2      2048                     // 2 x 64 f32
#define OFF_DOT     2560                     // 128 f32
#define OFF_A(s)    (4096  + (s) * 16384)    // A stages: 128 x 64 fp16 = 16K each
#define OFF_B(s)    (36864 + (s) * 32768)    // B stages: 256 x 64 fp16 = 32K each
#define OFF_H(c)    (4096  + (c) * 16384)    // h tiles alias stage region (dead then)
#define OFF_W2      102400                   // 4 chunks x [64][64] fp16 = 32K
#define OFF_U2      135168                   // 128 x 64 f32 = 32K
#define SMEM_BYTES  167936

// ---------------------------------------------------------------------------
// Device scratch (static)
// ---------------------------------------------------------------------------
__device__ __half g_w1t[2][H_DIM][D_IN];    // [u/i][h][d]  K-major, 4 MB
__device__ __half g_w2t[2][O_DIM][H_DIM];   // [u/i][o][h]  K-major, 64 KB

// ---------------------------------------------------------------------------
// Helpers (base sm_103-safe PTX: ldmatrix / mma.sync / cp.async)
// ---------------------------------------------------------------------------
#define SW128(x) ((x) ^ (((x) >> 3) & 0x70))

__device__ __forceinline__ uint32_t smem_u32(const void* p) {
    uint32_t a;
    asm("{ .reg .u64 t; cvta.to.shared.u64 t, %1; cvt.u32.u64 %0, t; }" : "=r"(a) : "l"(p));
    return a;
}

__device__ __forceinline__ void ldsm_x4(uint32_t addr, uint32_t r[4]) {
    asm volatile("ldmatrix.sync.aligned.m8n8.x4.shared.b16 {%0,%1,%2,%3}, [%4];"
                 : "=r"(r[0]), "=r"(r[1]), "=r"(r[2]), "=r"(r[3]) : "r"(addr));
}

__device__ __forceinline__ void mma16816(float c[4], const uint32_t a[4],
                                         uint32_t b0, uint32_t b1) {
    asm volatile(
        "mma.sync.aligned.m16n8k16.row.col.f32.f16.f16.f32 "
        "{%0,%1,%2,%3}, {%4,%5,%6,%7}, {%8,%9}, {%0,%1,%2,%3};"
        : "+f"(c[0]), "+f"(c[1]), "+f"(c[2]), "+f"(c[3])
        : "r"(a[0]), "r"(a[1]), "r"(a[2]), "r"(a[3]), "r"(b0), "r"(b1));
}

#define CP_ASYNC_16(dst, src) \
    asm volatile("cp.async.cg.shared.global [%0], [%1], 16;" \
                 :: "r"((uint32_t)(dst)), "l"(src) : "memory")
#define CP_ASYNC_COMMIT() asm volatile("cp.async.commit_group;" ::: "memory")
#define CP_ASYNC_WAIT_ALL() asm volatile("cp.async.wait_group 0;" ::: "memory")

// ---------------------------------------------------------------------------
// Weight prep (R9): coalesced 32x32 tile transpose, fp32 -> fp16 K-major
// ---------------------------------------------------------------------------
#define W1_TILES_PER_SET (128 * 8)   // (D/32) * (H/32)
#define W2_TILES_PER_SET (8 * 2)     // (H/32) * (O/32)

__global__ void prep_weights_kernel(const float* __restrict__ u_w1, const float* __restrict__ i_w1,
                                    const float* __restrict__ u_w2, const float* __restrict__ i_w2) {
    __shared__ float tile[32][33];
    const int tx = threadIdx.x & 31;
    const int ty = threadIdx.x >> 5;   // 0..7
    int b = blockIdx.x;

    if (b < 2 * W1_TILES_PER_SET) {
        const int which = b >= W1_TILES_PER_SET;
        if (which) b -= W1_TILES_PER_SET;
        const int d0 = (b >> 3) * 32;
        const int h0 = (b & 7) * 32;
        const float* src = which ? i_w1 : u_w1;
        #pragma unroll
        for (int dy = 0; dy < 4; dy++) {
            int d = d0 + ty + dy * 8;
            tile[ty + dy * 8][tx] = src[(size_t)d * H_DIM + h0 + tx];
        }
        __syncthreads();
        #pragma unroll
        for (int dy = 0; dy < 4; dy++) {
            int h = h0 + ty + dy * 8;
            g_w1t[which][h][d0 + tx] = __float2half_rn(tile[tx][ty + dy * 8]);
        }
    } else {
        b -= 2 * W1_TILES_PER_SET;
        const int which = b >= W2_TILES_PER_SET;
        if (which) b -= W2_TILES_PER_SET;
        const int h0 = (b >> 1) * 32;
        const int o0 = (b & 1) * 32;
        const float* src = which ? i_w2 : u_w2;
        #pragma unroll
        for (int hy = 0; hy < 4; hy++) {
            int h = h0 + ty + hy * 8;
            tile[ty + hy * 8][tx] = src[(size_t)h * O_DIM + o0 + tx];
        }
        __syncthreads();
        #pragma unroll
        for (int oy = 0; oy < 4; oy++) {
            int o = o0 + ty + oy * 8;
            g_w2t[which][o][h0 + tx] = __float2half_rn(tile[tx][ty + oy * 8]);
        }
    }
}

// ---------------------------------------------------------------------------
// A-path helpers: LDG chunk -> fp32 regs; cvt+STS regs -> SW128 stage
// ---------------------------------------------------------------------------
__device__ __forceinline__ void ldg_A(const float* __restrict__ x, int m0, int c,
                                      int tid, float4 v[4]) {
    #pragma unroll
    for (int k = 0; k < 4; k++) {
        int u = tid + k * NTHREADS;          // 0..2047 float4 units
        int row = u >> 4, col4 = u & 15;
        v[k] = *((const float4*)(x + (size_t)(m0 + row) * D_IN + c * KC) + col4);
    }
}

__device__ __forceinline__ void sts_A(char* smem, uint32_t aoff, int tid, const float4 v[4]) {
    #pragma unroll
    for (int k = 0; k < 4; k++) {
        int u = tid + k * NTHREADS;
        int row = u >> 4, col4 = u & 15;
        __half2 h01 = __floats2half2_rn(v[k].x, v[k].y);
        __half2 h23 = __floats2half2_rn(v[k].z, v[k].w);
        uint2 pk;
        pk.x = *(uint32_t*)&h01;
        pk.y = *(uint32_t*)&h23;
        *(uint2*)(smem + aoff + SW128((uint32_t)(row * 128 + col4 * 8))) = pk;
    }
}

__device__ __forceinline__ void ld_B(uint32_t sb, uint32_t boff, const __half* __restrict__ w1,
                                     int c, int tid) {
    #pragma unroll
    for (int k = 0; k < 4; k++) {
        int g = tid + k * NTHREADS;          // 0..2047 16B granules
        int h = g >> 3, gg = g & 7;
        CP_ASYNC_16(sb + boff + SW128((uint32_t)(h * 128 + gg * 16)),
                    w1 + (size_t)h * D_IN + c * KC + gg * 8);
    }
}

// One ks-block of layer-1 with cross-ks pipelining (R14), generalized for
// PER-WARP ks ROTATION: the block index j (0..3) drives buffer parity; the
// actual K position is kb_cur (runtime, = rotated ks * 32). At ng==3 the
// fragments for the NEXT rotated ks (kb_nxt) are prefetched.
// sa/sbb are pre-swizzled per-thread bases (R11 identity; kb only touches
// bits 5-6 so base ^ kb is the correct swizzled address).
__device__ __forceinline__ void compute_ks_pipe(uint32_t ah, uint32_t bt,
                                                int j, uint32_t kb_cur, uint32_t kb_nxt,
                                                bool has_next,
                                                uint32_t sa, uint32_t sbb,
                                                uint32_t a[2][2][4], uint32_t b[2][4],
                                                float cacc[2][8][4]) {
    const uint32_t skb = sbb ^ kb_cur;
    const int ab = j & 1;
    #pragma unroll
    for (int ng = 0; ng < 4; ng++) {
        const int cur = (j * 4 + ng) & 1;
        const int nxt = cur ^ 1;
        if (ng < 3) {
            ldsm_x4(bt + skb + (uint32_t)((ng + 1) * 2048), b[nxt]);
        } else if (has_next) {
            ldsm_x4(bt + (sbb ^ kb_nxt), b[nxt]);
            ldsm_x4(ah + (sa ^ kb_nxt),        a[ab ^ 1][0]);
            ldsm_x4(ah + (sa ^ kb_nxt) + 2048, a[ab ^ 1][1]);
        }
        mma16816(cacc[0][ng * 2 + 0], a[ab][0], b[cur][0], b[cur][1]);
        mma16816(cacc[1][ng * 2 + 0], a[ab][1], b[cur][0], b[cur][1]);
        mma16816(cacc[0][ng * 2 + 1], a[ab][0], b[cur][2], b[cur][3]);
        mma16816(cacc[1][ng * 2 + 1], a[ab][1], b[cur][2], b[cur][3]);
    }
}

// ---------------------------------------------------------------------------
// Main fused kernel: 512 threads, 16 warps (4M x 4N), M-tile 128
// ---------------------------------------------------------------------------
__global__ void __launch_bounds__(NTHREADS, 1)
llama_head_kernel(const float* __restrict__ user_emb,
                  const float* __restrict__ item_emb,
                  const float* __restrict__ u_b1, const float* __restrict__ i_b1,
                  const float* __restrict__ u_b2, const float* __restrict__ i_b2,
                  float* __restrict__ out) {
    extern __shared__ __align__(1024) char smem[];
    const uint32_t sb = smem_u32(smem);

    const int tid  = threadIdx.x;
    const int lane = tid & 31;
    const int wid  = tid >> 5;
    const int wm   = wid >> 2;          // 0..3  (M groups of 32 rows)
    const int wn   = wid & 3;           // 0..3  (N groups of 64 cols)
    const int m0   = blockIdx.x * TILE_M;
    const int lt   = lane >> 3;         // ldmatrix tile index 0..3
    const int lr   = lane & 7;          // ldmatrix row-in-tile
    const int qr   = lane >> 2;         // mma row within m8 group
    const int qc   = 2 * (lane & 3);    // mma col pair base

    const uint32_t a_row_base = (uint32_t)((wm * 32 + (lt & 1) * 8 + lr) * 128 + (lt >> 1) * 16);
    const uint32_t b_row_base = (uint32_t)((wn * 64 + (lt >> 1) * 8 + lr) * 128 + (lt & 1) * 16);
    const uint32_t sa  = SW128(a_row_base);   // pre-swizzled LDSM bases
    const uint32_t sbb = SW128(b_row_base);

    const uint32_t kb0 = (uint32_t)((wid & 3) * 32);   // per-warp ks rotation start
    const bool worder  = (wid & 1);                    // refill order alternation

    // ---- init: biases, dot buffer ----
    if (tid < 256) ((float*)(smem + OFF_B1))[tid] = u_b1[tid];
    else           ((float*)(smem + OFF_B1))[tid] = i_b1[tid - 256];
    if (tid < 64)        ((float*)(smem + OFF_B2))[tid] = u_b2[tid];
    else if (tid < 128)  ((float*)(smem + OFF_B2))[tid] = i_b2[tid - 64];
    if (tid < 128) ((float*)(smem + OFF_DOT))[tid] = 0.0f;

    for (int p = 0; p < 2; p++) {
        const float*  x  = p ? item_emb : user_emb;
        const __half* w1 = &g_w1t[p][0][0];
        const __half* w2 = &g_w2t[p][0][0];

        float cacc[2][8][4];
        #pragma unroll
        for (int i = 0; i < 2; i++)
            #pragma unroll
            for (int j = 0; j < 8; j++)
                #pragma unroll
                for (int q = 0; q < 4; q++) cacc[i][j][q] = 0.0f;

        // ---- prologue ----
        float4 rA[4];
        {
            ldg_A(x, m0, 0, tid, rA);
            sts_A(smem, OFF_A(0), tid, rA);
            // B chunk 0 + THIS phase's w2 tiles (w2 reloaded every phase —
            // single OFF_W2 buffer; phase 1 needs i_w2).
            ld_B(sb, OFF_B(0), w1, 0, tid);
            #pragma unroll
            for (int k = 0; k < 4; k++) {
                int g  = tid + k * NTHREADS;      // 0..2047
                int hc = g >> 9;
                int rr = g & 511;
                int o  = rr >> 3;
                int gg = rr & 7;
                const __half* src = w2 + (size_t)o * H_DIM + hc * KC + gg * 8;
                uint32_t dst = sb + OFF_W2 + hc * 8192 + SW128((uint32_t)(o * 128 + gg * 16));
                CP_ASYNC_16(dst, src);
            }
            CP_ASYNC_COMMIT();
            ldg_A(x, m0, 1, tid, rA);   // chunk 1 -> regs, consumed next iter
        }

        // ====== layer-1 mainloop: rotated ks traversal + alternated refill ======
        for (int c = 0; c < NCHUNK; c++) {
            const int s  = c & 1;
            const int sn = s ^ 1;

            CP_ASYNC_WAIT_ALL();     // my B(c) (and W2 on first iter) complete
            __syncthreads();         // all threads' B(c) visible; compute(c-1) done

            const uint32_t ah = sb + OFF_A(s);
            const uint32_t bt = sb + OFF_B(s);
            const bool refill = (c + 1 < NCHUNK);

            // chunk-top preload at this warp's rotated ks
            uint32_t a[2][2][4];
            uint32_t b[2][4];
            ldsm_x4(ah + (sa ^ kb0),        a[0][0]);
            ldsm_x4(ah + (sa ^ kb0) + 2048, a[0][1]);
            ldsm_x4(bt + (sbb ^ kb0),       b[0]);

            uint32_t kb_c = kb0;
            uint32_t kb_n = (kb_c + 32) & 96;

            compute_ks_pipe(ah, bt, 0, kb_c, kb_n, true, sa, sbb, a, b, cacc);
            if (refill) {
                if (worder) { ld_B(sb, OFF_B(sn), w1, c + 1, tid); CP_ASYNC_COMMIT(); }
                else        { sts_A(smem, OFF_A(sn), tid, rA); }
            }
            kb_c = kb_n; kb_n = (kb_c + 32) & 96;
            compute_ks_pipe(ah, bt, 1, kb_c, kb_n, true, sa, sbb, a, b, cacc);
            if (refill) {
                if (worder) { sts_A(smem, OFF_A(sn), tid, rA); }
                else        { ld_B(sb, OFF_B(sn), w1, c + 1, tid); CP_ASYNC_COMMIT(); }
            }
            kb_c = kb_n; kb_n = (kb_c + 32) & 96;
            compute_ks_pipe(ah, bt, 2, kb_c, kb_n, true, sa, sbb, a, b, cacc);
            if (c + 2 < NCHUNK) ldg_A(x, m0, c + 2, tid, rA);   // A(c+2) -> regs
            kb_c = kb_n;
            compute_ks_pipe(ah, bt, 3, kb_c, 0, false, sa, sbb, a, b, cacc);
        }
        __syncthreads();   // all warps done reading stages before H overwrites them

        // ============ layer-1 epilogue: bias + relu + fp16 h tiles ============
        {
            const float* b1s = (const float*)(smem + OFF_B1 + p * 1024);
            #pragma unroll
            for (int mi = 0; mi < 2; mi++) {
                const int r0 = wm * 32 + mi * 16 + qr;
                #pragma unroll
                for (int g = 0; g < 8; g++) {
                    const int nc = wn * 64 + g * 8 + qc;
                    float bb0 = b1s[nc], bb1 = b1s[nc + 1];
                    float v00 = fmaxf(cacc[mi][g][0] + bb0, 0.0f);
                    float v01 = fmaxf(cacc[mi][g][1] + bb1, 0.0f);
                    float v10 = fmaxf(cacc[mi][g][2] + bb0, 0.0f);
                    float v11 = fmaxf(cacc[mi][g][3] + bb1, 0.0f);
                    __half2 hv0 = __floats2half2_rn(v00, v01);
                    __half2 hv1 = __floats2half2_rn(v10, v11);
                    const int hc = nc >> 6, colc = nc & 63;
                    *(uint32_t*)(smem + OFF_H(hc) + SW128((uint32_t)(r0 * 128 + colc * 2)))
                        = *(uint32_t*)&hv0;
                    *(uint32_t*)(smem + OFF_H(hc) + SW128((uint32_t)((r0 + 8) * 128 + colc * 2)))
                        = *(uint32_t*)&hv1;
                }
            }
        }
        __syncthreads();

        // ===================== layer-2: [128,64] = h[128,256] x w2t ===========
        float c2[2][2][4];
        #pragma unroll
        for (int i = 0; i < 2; i++)
            #pragma unroll
            for (int j = 0; j < 2; j++)
                #pragma unroll
                for (int q = 0; q < 4; q++) c2[i][j][q] = 0.0f;

        #pragma unroll
        for (int ks = 0; ks < 16; ks++) {
            const int hc = ks >> 2, k0 = (ks & 3) * 16;
            uint32_t a[2][4], b[4];
            #pragma unroll
            for (int mi = 0; mi < 2; mi++) {
                uint32_t aoff = SW128((uint32_t)(
                    (wm * 32 + mi * 16 + (lt & 1) * 8 + lr) * 128 +
                    (k0 + (lt >> 1) * 8) * 2));
                ldsm_x4(sb + OFF_H(hc) + aoff, a[mi]);
            }
            uint32_t boff = SW128((uint32_t)(
                (wn * 16 + (lt >> 1) * 8 + lr) * 128 + (k0 + (lt & 1) * 8) * 2));
            ldsm_x4(sb + OFF_W2 + hc * 8192 + boff, b);
            #pragma unroll
            for (int mi = 0; mi < 2; mi++) {
                mma16816(c2[mi][0], a[mi], b[0], b[1]);
                mma16816(c2[mi][1], a[mi], b[2], b[3]);
            }
        }

        // ===================== layer-2 epilogue ===============================
        if (p == 0) {
            const float* b2s = (const float*)(smem + OFF_B2);
            float* u2 = (float*)(smem + OFF_U2);
            #pragma unroll
            for (int mi = 0; mi < 2; mi++) {
                const int r0 = wm * 32 + mi * 16 + qr;
                #pragma unroll
                for (int g = 0; g < 2; g++) {
                    const int n = wn * 16 + g * 8 + qc;
                    u2[r0 * 64 + n]           = c2[mi][g][0] + b2s[n];
                    u2[r0 * 64 + n + 1]       = c2[mi][g][1] + b2s[n + 1];
                    u2[(r0 + 8) * 64 + n]     = c2[mi][g][2] + b2s[n];
                    u2[(r0 + 8) * 64 + n + 1] = c2[mi][g][3] + b2s[n + 1];
                }
            }
            __syncthreads();   // u2 complete; all H/W2 reads done before phase-1 refills
        } else {
            const float* b2s = (const float*)(smem + OFF_B2 + 256);
            const float* u2 = (const float*)(smem + OFF_U2);
            float* dotb = (float*)(smem + OFF_DOT);
            #pragma unroll
            for (int mi = 0; mi < 2; mi++) {
                const int r0 = wm * 32 + mi * 16 + qr;
                float pr0 = 0.0f, pr1 = 0.0f;
                #pragma unroll
                for (int g = 0; g < 2; g++) {
                    const int n = wn * 16 + g * 8 + qc;
                    float bv0 = b2s[n], bv1 = b2s[n + 1];
                    pr0 += (c2[mi][g][0] + bv0) * u2[r0 * 64 + n];
                    pr0 += (c2[mi][g][1] + bv1) * u2[r0 * 64 + n + 1];
                    pr1 += (c2[mi][g][2] + bv0) * u2[(r0 + 8) * 64 + n];
                    pr1 += (c2[mi][g][3] + bv1) * u2[(r0 + 8) * 64 + n + 1];
                }
                pr0 += __shfl_xor_sync(0xFFFFFFFF, pr0, 1);
                pr0 += __shfl_xor_sync(0xFFFFFFFF, pr0, 2);
                pr1 += __shfl_xor_sync(0xFFFFFFFF, pr1, 1);
                pr1 += __shfl_xor_sync(0xFFFFFFFF, pr1, 2);
                if ((lane & 3) == 0) {
                    atomicAdd(&dotb[r0], pr0);
                    atomicAdd(&dotb[r0 + 8], pr1);
                }
            }
            __syncthreads();
        }
    }

    // ===================== final: sigmoid(dot) =====================
    if (tid < 128) {
        float d = ((const float*)(smem + OFF_DOT))[tid];
        out[m0 + tid] = 1.0f / (1.0f + __expf(-d));
    }
}

// ---------------------------------------------------------------------------
// kernel_launch
// ---------------------------------------------------------------------------
extern "C" void kernel_launch(void* const* d_in, const int* in_sizes, int n_in,
                              void* d_out, int out_size) {
    const float* user_emb = (const float*)d_in[0];
    const float* item_emb = (const float*)d_in[1];
    const float* u_w1 = (const float*)d_in[2];
    const float* u_b1 = (const float*)d_in[3];
    const float* u_w2 = (const float*)d_in[4];
    const float* u_b2 = (const float*)d_in[5];
    const float* i_w1 = (const float*)d_in[6];
    const float* i_b1 = (const float*)d_in[7];
    const float* i_w2 = (const float*)d_in[8];
    const float* i_b2 = (const float*)d_in[9];
    float* out = (float*)d_out;

    cudaFuncSetAttribute(llama_head_kernel,
                         cudaFuncAttributeMaxDynamicSharedMemorySize, SMEM_BYTES);

    const int prep_blocks = 2 * W1_TILES_PER_SET + 2 * W2_TILES_PER_SET;
    prep_weights_kernel<<<prep_blocks, 256>>>(u_w1, i_w1, u_w2, i_w2);

    llama_head_kernel<<<NROWS / TILE_M, NTHREADS, SMEM_BYTES>>>(
        user_emb, item_emb, u_b1, i_b1, u_b2, i_b2, out);
}

// round 16
// speedup vs baseline: 1.0402x; 1.0402x over previous
#include <cuda_runtime.h>
#include <cuda_fp16.h>
#include <cstdint>

// ---------------------------------------------------------------------------
// Problem constants
// ---------------------------------------------------------------------------
#define D_IN    4096
#define H_DIM   256
#define O_DIM   64
#define KC      64        // K-chunk: 64 halves = 128 B rows (SW128)
#define NCHUNK  64        // 4096 / 64
#define TILE_M  128
#define NROWS   32768
#define NTHREADS 512

// ---------------------------------------------------------------------------
// SMEM layout (bytes from dynamic smem base; base is 1024-aligned)
// ---------------------------------------------------------------------------
#define OFF_B1      0                        // 2 x 256 f32
#define OFF_B2      2048                     // 2 x 64 f32
#define OFF_DOT     2560                     // 128 f32
#define OFF_A(s)    (4096  + (s) * 16384)    // A stages: 128 x 64 fp16 = 16K each
#define OFF_B(s)    (36864 + (s) * 32768)    // B stages: 256 x 64 fp16 = 32K each
#define OFF_H(c)    (4096  + (c) * 16384)    // h tiles alias stage region (dead then)
#define OFF_W2      102400                   // 4 chunks x [64][64] fp16 = 32K
#define OFF_U2      135168                   // 128 x 64 f32 = 32K
#define SMEM_BYTES  167936

// ---------------------------------------------------------------------------
// Device scratch (static)
// ---------------------------------------------------------------------------
__device__ __half g_w1t[2][H_DIM][D_IN];    // [u/i][h][d]  K-major, 4 MB
__device__ __half g_w2t[2][O_DIM][H_DIM];   // [u/i][o][h]  K-major, 64 KB

// ---------------------------------------------------------------------------
// Helpers (base sm_103-safe PTX: ldmatrix / mma.sync / cp.async)
// ---------------------------------------------------------------------------
#define SW128(x) ((x) ^ (((x) >> 3) & 0x70))

__device__ __forceinline__ uint32_t smem_u32(const void* p) {
    uint32_t a;
    asm("{ .reg .u64 t; cvta.to.shared.u64 t, %1; cvt.u32.u64 %0, t; }" : "=r"(a) : "l"(p));
    return a;
}

__device__ __forceinline__ void ldsm_x4(uint32_t addr, uint32_t r[4]) {
    asm volatile("ldmatrix.sync.aligned.m8n8.x4.shared.b16 {%0,%1,%2,%3}, [%4];"
                 : "=r"(r[0]), "=r"(r[1]), "=r"(r[2]), "=r"(r[3]) : "r"(addr));
}

__device__ __forceinline__ void mma16816(float c[4], const uint32_t a[4],
                                         uint32_t b0, uint32_t b1) {
    asm volatile(
        "mma.sync.aligned.m16n8k16.row.col.f32.f16.f16.f32 "
        "{%0,%1,%2,%3}, {%4,%5,%6,%7}, {%8,%9}, {%0,%1,%2,%3};"
        : "+f"(c[0]), "+f"(c[1]), "+f"(c[2]), "+f"(c[3])
        : "r"(a[0]), "r"(a[1]), "r"(a[2]), "r"(a[3]), "r"(b0), "r"(b1));
}

#define CP_ASYNC_16(dst, src) \
    asm volatile("cp.async.cg.shared.global [%0], [%1], 16;" \
                 :: "r"((uint32_t)(dst)), "l"(src) : "memory")
#define CP_ASYNC_COMMIT() asm volatile("cp.async.commit_group;" ::: "memory")
#define CP_ASYNC_WAIT_ALL() asm volatile("cp.async.wait_group 0;" ::: "memory")

// ---------------------------------------------------------------------------
// Weight prep (R9): coalesced 32x32 tile transpose, fp32 -> fp16 K-major
// ---------------------------------------------------------------------------
#define W1_TILES_PER_SET (128 * 8)   // (D/32) * (H/32)
#define W2_TILES_PER_SET (8 * 2)     // (H/32) * (O/32)

__global__ void prep_weights_kernel(const float* __restrict__ u_w1, const float* __restrict__ i_w1,
                                    const float* __restrict__ u_w2, const float* __restrict__ i_w2) {
    __shared__ float tile[32][33];
    const int tx = threadIdx.x & 31;
    const int ty = threadIdx.x >> 5;   // 0..7
    int b = blockIdx.x;

    if (b < 2 * W1_TILES_PER_SET) {
        const int which = b >= W1_TILES_PER_SET;
        if (which) b -= W1_TILES_PER_SET;
        const int d0 = (b >> 3) * 32;
        const int h0 = (b & 7) * 32;
        const float* src = which ? i_w1 : u_w1;
        #pragma unroll
        for (int dy = 0; dy < 4; dy++) {
            int d = d0 + ty + dy * 8;
            tile[ty + dy * 8][tx] = src[(size_t)d * H_DIM + h0 + tx];
        }
        __syncthreads();
        #pragma unroll
        for (int dy = 0; dy < 4; dy++) {
            int h = h0 + ty + dy * 8;
            g_w1t[which][h][d0 + tx] = __float2half_rn(tile[tx][ty + dy * 8]);
        }
    } else {
        b -= 2 * W1_TILES_PER_SET;
        const int which = b >= W2_TILES_PER_SET;
        if (which) b -= W2_TILES_PER_SET;
        const int h0 = (b >> 1) * 32;
        const int o0 = (b & 1) * 32;
        const float* src = which ? i_w2 : u_w2;
        #pragma unroll
        for (int hy = 0; hy < 4; hy++) {
            int h = h0 + ty + hy * 8;
            tile[ty + hy * 8][tx] = src[(size_t)h * O_DIM + o0 + tx];
        }
        __syncthreads();
        #pragma unroll
        for (int oy = 0; oy < 4; oy++) {
            int o = o0 + ty + oy * 8;
            g_w2t[which][o][h0 + tx] = __float2half_rn(tile[tx][ty + oy * 8]);
        }
    }
}

// ---------------------------------------------------------------------------
// A-path helpers: LDG chunk -> fp32 regs; cvt+STS regs -> SW128 stage
// ---------------------------------------------------------------------------
__device__ __forceinline__ void ldg_A(const float* __restrict__ x, int m0, int c,
                                      int tid, float4 v[4]) {
    #pragma unroll
    for (int k = 0; k < 4; k++) {
        int u = tid + k * NTHREADS;          // 0..2047 float4 units
        int row = u >> 4, col4 = u & 15;
        v[k] = *((const float4*)(x + (size_t)(m0 + row) * D_IN + c * KC) + col4);
    }
}

__device__ __forceinline__ void sts_A(char* smem, uint32_t aoff, int tid, const float4 v[4]) {
    #pragma unroll
    for (int k = 0; k < 4; k++) {
        int u = tid + k * NTHREADS;
        int row = u >> 4, col4 = u & 15;
        __half2 h01 = __floats2half2_rn(v[k].x, v[k].y);
        __half2 h23 = __floats2half2_rn(v[k].z, v[k].w);
        uint2 pk;
        pk.x = *(uint32_t*)&h01;
        pk.y = *(uint32_t*)&h23;
        *(uint2*)(smem + aoff + SW128((uint32_t)(row * 128 + col4 * 8))) = pk;
    }
}

__device__ __forceinline__ void ld_B(uint32_t sb, uint32_t boff, const __half* __restrict__ w1,
                                     int c, int tid) {
    #pragma unroll
    for (int k = 0; k < 4; k++) {
        int g = tid + k * NTHREADS;          // 0..2047 16B granules
        int h = g >> 3, gg = g & 7;
        CP_ASYNC_16(sb + boff + SW128((uint32_t)(h * 128 + gg * 16)),
                    w1 + (size_t)h * D_IN + c * KC + gg * 8);
    }
}

// One ks-block of layer-1 with CROSS-KS pipelining (R14): fragments for
// (ks, ng+1) — and at ng==3, for (ks+1, 0) including both A fragments — are
// loaded BEFORE the 4 MMAs of the current step, so every LDSM after the
// chunk's first three has ≥4 MMAs (~32cyc) of tensor back-pressure covering it.
// a[2][2][4] double-buffered on ks&1; b[2][4] alternates per (ks*4+ng)&1.
// sa/sbb are pre-swizzled per-thread bases (R11 identity); all kb offsets are
// compile-time constants (R15 lesson: runtime kb defeats constant folding).
__device__ __forceinline__ void compute_ks_pipe(uint32_t ah, uint32_t bt, int ks,
                                                uint32_t sa, uint32_t sbb,
                                                uint32_t a[2][2][4], uint32_t b[2][4],
                                                float cacc[2][8][4]) {
    const uint32_t skb = sbb ^ (uint32_t)(ks * 32);
    const int ab = ks & 1;
    #pragma unroll
    for (int ng = 0; ng < 4; ng++) {
        const int cur = (ks * 4 + ng) & 1;
        const int nxt = cur ^ 1;
        if (ng < 3) {
            ldsm_x4(bt + skb + (uint32_t)((ng + 1) * 2048), b[nxt]);
        } else if (ks < 3) {
            const uint32_t knb = (uint32_t)((ks + 1) * 32);
            ldsm_x4(bt + (sbb ^ knb), b[nxt]);
            ldsm_x4(ah + (sa ^ knb),        a[ab ^ 1][0]);
            ldsm_x4(ah + (sa ^ knb) + 2048, a[ab ^ 1][1]);
        }
        mma16816(cacc[0][ng * 2 + 0], a[ab][0], b[cur][0], b[cur][1]);
        mma16816(cacc[1][ng * 2 + 0], a[ab][1], b[cur][0], b[cur][1]);
        mma16816(cacc[0][ng * 2 + 1], a[ab][0], b[cur][2], b[cur][3]);
        mma16816(cacc[1][ng * 2 + 1], a[ab][1], b[cur][2], b[cur][3]);
    }
}

// ---------------------------------------------------------------------------
// Main fused kernel: 512 threads, 16 warps (4M x 4N), M-tile 128
// ---------------------------------------------------------------------------
__global__ void __launch_bounds__(NTHREADS, 1)
llama_head_kernel(const float* __restrict__ user_emb,
                  const float* __restrict__ item_emb,
                  const float* __restrict__ u_b1, const float* __restrict__ i_b1,
                  const float* __restrict__ u_b2, const float* __restrict__ i_b2,
                  float* __restrict__ out) {
    extern __shared__ __align__(1024) char smem[];
    const uint32_t sb = smem_u32(smem);

    const int tid  = threadIdx.x;
    const int lane = tid & 31;
    const int wid  = tid >> 5;
    const int wm   = wid >> 2;          // 0..3  (M groups of 32 rows)
    const int wn   = wid & 3;           // 0..3  (N groups of 64 cols)
    const int m0   = blockIdx.x * TILE_M;
    const int lt   = lane >> 3;         // ldmatrix tile index 0..3
    const int lr   = lane & 7;          // ldmatrix row-in-tile
    const int qr   = lane >> 2;         // mma row within m8 group
    const int qc   = 2 * (lane & 3);    // mma col pair base

    const uint32_t a_row_base = (uint32_t)((wm * 32 + (lt & 1) * 8 + lr) * 128 + (lt >> 1) * 16);
    const uint32_t b_row_base = (uint32_t)((wn * 64 + (lt >> 1) * 8 + lr) * 128 + (lt & 1) * 16);
    const uint32_t sa  = SW128(a_row_base);   // pre-swizzled LDSM bases
    const uint32_t sbb = SW128(b_row_base);

    // Phase-0 chunk-0 prefetch: issued BEFORE the init block so the DRAM
    // latency is covered by the bias loads / dot init below.
    float4 rA[4];
    ldg_A(user_emb, m0, 0, tid, rA);

    // ---- init: biases, dot buffer ----
    if (tid < 256) ((float*)(smem + OFF_B1))[tid] = u_b1[tid];
    else           ((float*)(smem + OFF_B1))[tid] = i_b1[tid - 256];
    if (tid < 64)        ((float*)(smem + OFF_B2))[tid] = u_b2[tid];
    else if (tid < 128)  ((float*)(smem + OFF_B2))[tid] = i_b2[tid - 64];
    if (tid < 128) ((float*)(smem + OFF_DOT))[tid] = 0.0f;

    for (int p = 0; p < 2; p++) {
        const float*  x  = p ? item_emb : user_emb;
        const __half* w1 = &g_w1t[p][0][0];
        const __half* w2 = &g_w2t[p][0][0];

        float cacc[2][8][4];
        #pragma unroll
        for (int i = 0; i < 2; i++)
            #pragma unroll
            for (int j = 0; j < 8; j++)
                #pragma unroll
                for (int q = 0; q < 4; q++) cacc[i][j][q] = 0.0f;

        // ---- prologue: rA already holds THIS phase's chunk 0 (prefetched) ----
        {
            sts_A(smem, OFF_A(0), tid, rA);
            // B chunk 0 + THIS phase's w2 tiles (w2 reloaded every phase —
            // single OFF_W2 buffer; phase 1 needs i_w2).
            ld_B(sb, OFF_B(0), w1, 0, tid);
            #pragma unroll
            for (int k = 0; k < 4; k++) {
                int g  = tid + k * NTHREADS;      // 0..2047
                int hc = g >> 9;
                int rr = g & 511;
                int o  = rr >> 3;
                int gg = rr & 7;
                const __half* src = w2 + (size_t)o * H_DIM + hc * KC + gg * 8;
                uint32_t dst = sb + OFF_W2 + hc * 8192 + SW128((uint32_t)(o * 128 + gg * 16));
                CP_ASYNC_16(dst, src);
            }
            CP_ASYNC_COMMIT();
            ldg_A(x, m0, 1, tid, rA);   // chunk 1 -> regs, consumed next iter
        }

        // ====== layer-1 mainloop: cross-ks pipelined compute ======
        for (int c = 0; c < NCHUNK; c++) {
            const int s  = c & 1;
            const int sn = s ^ 1;

            CP_ASYNC_WAIT_ALL();     // my B(c) (and W2 on first iter) complete
            __syncthreads();         // all threads' B(c) visible; compute(c-1) done

            const uint32_t ah = sb + OFF_A(s);
            const uint32_t bt = sb + OFF_B(s);
            const bool refill = (c + 1 < NCHUNK);

            // chunk-top preload: the only 3 exposed LDSMs per chunk
            uint32_t a[2][2][4];
            uint32_t b[2][4];
            ldsm_x4(ah + sa,        a[0][0]);
            ldsm_x4(ah + sa + 2048, a[0][1]);
            ldsm_x4(bt + sbb,       b[0]);

            compute_ks_pipe(ah, bt, 0, sa, sbb, a, b, cacc);
            if (refill) sts_A(smem, OFF_A(sn), tid, rA);        // A(c+1) regs->smem
            compute_ks_pipe(ah, bt, 1, sa, sbb, a, b, cacc);
            if (refill) {
                ld_B(sb, OFF_B(sn), w1, c + 1, tid);            // B(c+1) via cp.async
                CP_ASYNC_COMMIT();
            }
            compute_ks_pipe(ah, bt, 2, sa, sbb, a, b, cacc);
            if (c + 2 < NCHUNK) ldg_A(x, m0, c + 2, tid, rA);   // A(c+2) -> regs
            compute_ks_pipe(ah, bt, 3, sa, sbb, a, b, cacc);
        }
        // Phase-1 chunk-0 prefetch: rA is dead here; the whole phase-0
        // epilogue + layer-2 below covers the DRAM latency.
        if (p == 0) ldg_A(item_emb, m0, 0, tid, rA);
        __syncthreads();   // all warps done reading stages before H overwrites them

        // ============ layer-1 epilogue: bias + relu + fp16 h tiles ============
        {
            const float* b1s = (const float*)(smem + OFF_B1 + p * 1024);
            #pragma unroll
            for (int mi = 0; mi < 2; mi++) {
                const int r0 = wm * 32 + mi * 16 + qr;
                #pragma unroll
                for (int g = 0; g < 8; g++) {
                    const int nc = wn * 64 + g * 8 + qc;
                    float bb0 = b1s[nc], bb1 = b1s[nc + 1];
                    float v00 = fmaxf(cacc[mi][g][0] + bb0, 0.0f);
                    float v01 = fmaxf(cacc[mi][g][1] + bb1, 0.0f);
                    float v10 = fmaxf(cacc[mi][g][2] + bb0, 0.0f);
                    float v11 = fmaxf(cacc[mi][g][3] + bb1, 0.0f);
                    __half2 hv0 = __floats2half2_rn(v00, v01);
                    __half2 hv1 = __floats2half2_rn(v10, v11);
                    const int hc = nc >> 6, colc = nc & 63;
                    *(uint32_t*)(smem + OFF_H(hc) + SW128((uint32_t)(r0 * 128 + colc * 2)))
                        = *(uint32_t*)&hv0;
                    *(uint32_t*)(smem + OFF_H(hc) + SW128((uint32_t)((r0 + 8) * 128 + colc * 2)))
                        = *(uint32_t*)&hv1;
                }
            }
        }
        __syncthreads();

        // ===================== layer-2: [128,64] = h[128,256] x w2t ===========
        float c2[2][2][4];
        #pragma unroll
        for (int i = 0; i < 2; i++)
            #pragma unroll
            for (int j = 0; j < 2; j++)
                #pragma unroll
                for (int q = 0; q < 4; q++) c2[i][j][q] = 0.0f;

        #pragma unroll
        for (int ks = 0; ks < 16; ks++) {
            const int hc = ks >> 2, k0 = (ks & 3) * 16;
            uint32_t a[2][4], b[4];
            #pragma unroll
            for (int mi = 0; mi < 2; mi++) {
                uint32_t aoff = SW128((uint32_t)(
                    (wm * 32 + mi * 16 + (lt & 1) * 8 + lr) * 128 +
                    (k0 + (lt >> 1) * 8) * 2));
                ldsm_x4(sb + OFF_H(hc) + aoff, a[mi]);
            }
            uint32_t boff = SW128((uint32_t)(
                (wn * 16 + (lt >> 1) * 8 + lr) * 128 + (k0 + (lt & 1) * 8) * 2));
            ldsm_x4(sb + OFF_W2 + hc * 8192 + boff, b);
            #pragma unroll
            for (int mi = 0; mi < 2; mi++) {
                mma16816(c2[mi][0], a[mi], b[0], b[1]);
                mma16816(c2[mi][1], a[mi], b[2], b[3]);
            }
        }

        // ===================== layer-2 epilogue ===============================
        if (p == 0) {
            const float* b2s = (const float*)(smem + OFF_B2);
            float* u2 = (float*)(smem + OFF_U2);
            #pragma unroll
            for (int mi = 0; mi < 2; mi++) {
                const int r0 = wm * 32 + mi * 16 + qr;
                #pragma unroll
                for (int g = 0; g < 2; g++) {
                    const int n = wn * 16 + g * 8 + qc;
                    u2[r0 * 64 + n]           = c2[mi][g][0] + b2s[n];
                    u2[r0 * 64 + n + 1]       = c2[mi][g][1] + b2s[n + 1];
                    u2[(r0 + 8) * 64 + n]     = c2[mi][g][2] + b2s[n];
                    u2[(r0 + 8) * 64 + n + 1] = c2[mi][g][3] + b2s[n + 1];
                }
            }
            __syncthreads();   // u2 complete; all H/W2 reads done before phase-1 refills
        } else {
            const float* b2s = (const float*)(smem + OFF_B2 + 256);
            const float* u2 = (const float*)(smem + OFF_U2);
            float* dotb = (float*)(smem + OFF_DOT);
            #pragma unroll
            for (int mi = 0; mi < 2; mi++) {
                const int r0 = wm * 32 + mi * 16 + qr;
                float pr0 = 0.0f, pr1 = 0.0f;
                #pragma unroll
                for (int g = 0; g < 2; g++) {
                    const int n = wn * 16 + g * 8 + qc;
                    float bv0 = b2s[n], bv1 = b2s[n + 1];
                    pr0 += (c2[mi][g][0] + bv0) * u2[r0 * 64 + n];
                    pr0 += (c2[mi][g][1] + bv1) * u2[r0 * 64 + n + 1];
                    pr1 += (c2[mi][g][2] + bv0) * u2[(r0 + 8) * 64 + n];
                    pr1 += (c2[mi][g][3] + bv1) * u2[(r0 + 8) * 64 + n + 1];
                }
                pr0 += __shfl_xor_sync(0xFFFFFFFF, pr0, 1);
                pr0 += __shfl_xor_sync(0xFFFFFFFF, pr0, 2);
                pr1 += __shfl_xor_sync(0xFFFFFFFF, pr1, 1);
                pr1 += __shfl_xor_sync(0xFFFFFFFF, pr1, 2);
                if ((lane & 3) == 0) {
                    atomicAdd(&dotb[r0], pr0);
                    atomicAdd(&dotb[r0 + 8], pr1);
                }
            }
            __syncthreads();
        }
    }

    // ===================== final: sigmoid(dot) =====================
    if (tid < 128) {
        float d = ((const float*)(smem + OFF_DOT))[tid];
        out[m0 + tid] = 1.0f / (1.0f + __expf(-d));
    }
}

// ---------------------------------------------------------------------------
// kernel_launch
// ---------------------------------------------------------------------------
extern "C" void kernel_launch(void* const* d_in, const int* in_sizes, int n_in,
                              void* d_out, int out_size) {
    const float* user_emb = (const float*)d_in[0];
    const float* item_emb = (const float*)d_in[1];
    const float* u_w1 = (const float*)d_in[2];
    const float* u_b1 = (const float*)d_in[3];
    const float* u_w2 = (const float*)d_in[4];
    const float* u_b2 = (const float*)d_in[5];
    const float* i_w1 = (const float*)d_in[6];
    const float* i_b1 = (const float*)d_in[7];
    const float* i_w2 = (const float*)d_in[8];
    const float* i_b2 = (const float*)d_in[9];
    float* out = (float*)d_out;

    cudaFuncSetAttribute(llama_head_kernel,
                         cudaFuncAttributeMaxDynamicSharedMemorySize, SMEM_BYTES);

    const int prep_blocks = 2 * W1_TILES_PER_SET + 2 * W2_TILES_PER_SET;
    prep_weights_kernel<<<prep_blocks, 256>>>(u_w1, i_w1, u_w2, i_w2);

    llama_head_kernel<<<NROWS / TILE_M, NTHREADS, SMEM_BYTES>>>(
        user_emb, item_emb, u_b1, i_b1, u_b2, i_b2, out);
}

// round 17
// speedup vs baseline: 1.0771x; 1.0355x over previous
#include <cuda_runtime.h>
#include <cuda_fp16.h>
#include <cstdint>

// ---------------------------------------------------------------------------
// Problem constants
// ---------------------------------------------------------------------------
#define D_IN    4096
#define H_DIM   256
#define O_DIM   64
#define KC      64        // K-chunk: 64 halves = 128 B rows (SW128)
#define NCHUNK  64        // 4096 / 64
#define TILE_M  128
#define NROWS   32768
#define NTHREADS 512

// ---------------------------------------------------------------------------
// SMEM layout (bytes from dynamic smem base; base is 1024-aligned)
// ---------------------------------------------------------------------------
#define OFF_B1      0                        // 2 x 256 f32
#define OFF_B2      2048                     // 2 x 64 f32
#define OFF_DOT     2560                     // 128 f32
#define OFF_A(s)    (4096  + (s) * 16384)    // A stages: 128 x 64 fp16 = 16K each
#define OFF_B(s)    (36864 + (s) * 32768)    // B stages: 256 x 64 fp16 = 32K each
#define OFF_H(c)    (4096  + (c) * 16384)    // h tiles alias stage region (dead then)
#define OFF_W2      102400                   // 4 chunks x [64][64] fp16 = 32K
#define OFF_U2      135168                   // 128 x 64 f32 = 32K
#define SMEM_BYTES  167936

// ---------------------------------------------------------------------------
// Device scratch (static)
// ---------------------------------------------------------------------------
__device__ __half g_w1t[2][H_DIM][D_IN];    // [u/i][h][d]  K-major, 4 MB
__device__ __half g_w2t[2][O_DIM][H_DIM];   // [u/i][o][h]  K-major, 64 KB

// ---------------------------------------------------------------------------
// Helpers (base sm_103-safe PTX: ldmatrix / mma.sync / cp.async)
// ---------------------------------------------------------------------------
#define SW128(x) ((x) ^ (((x) >> 3) & 0x70))

__device__ __forceinline__ uint32_t smem_u32(const void* p) {
    uint32_t a;
    asm("{ .reg .u64 t; cvta.to.shared.u64 t, %1; cvt.u32.u64 %0, t; }" : "=r"(a) : "l"(p));
    return a;
}

__device__ __forceinline__ void ldsm_x4(uint32_t addr, uint32_t r[4]) {
    asm volatile("ldmatrix.sync.aligned.m8n8.x4.shared.b16 {%0,%1,%2,%3}, [%4];"
                 : "=r"(r[0]), "=r"(r[1]), "=r"(r[2]), "=r"(r[3]) : "r"(addr));
}

__device__ __forceinline__ void mma16816(float c[4], const uint32_t a[4],
                                         uint32_t b0, uint32_t b1) {
    asm volatile(
        "mma.sync.aligned.m16n8k16.row.col.f32.f16.f16.f32 "
        "{%0,%1,%2,%3}, {%4,%5,%6,%7}, {%8,%9}, {%0,%1,%2,%3};"
        : "+f"(c[0]), "+f"(c[1]), "+f"(c[2]), "+f"(c[3])
        : "r"(a[0]), "r"(a[1]), "r"(a[2]), "r"(a[3]), "r"(b0), "r"(b1));
}

#define CP_ASYNC_16(dst, src) \
    asm volatile("cp.async.cg.shared.global [%0], [%1], 16;" \
                 :: "r"((uint32_t)(dst)), "l"(src) : "memory")
#define CP_ASYNC_COMMIT() asm volatile("cp.async.commit_group;" ::: "memory")
#define CP_ASYNC_WAIT_ALL() asm volatile("cp.async.wait_group 0;" ::: "memory")

// ---------------------------------------------------------------------------
// Weight prep (R9): coalesced 32x32 tile transpose, fp32 -> fp16 K-major
// ---------------------------------------------------------------------------
#define W1_TILES_PER_SET (128 * 8)   // (D/32) * (H/32)
#define W2_TILES_PER_SET (8 * 2)     // (H/32) * (O/32)

__global__ void prep_weights_kernel(const float* __restrict__ u_w1, const float* __restrict__ i_w1,
                                    const float* __restrict__ u_w2, const float* __restrict__ i_w2) {
    __shared__ float tile[32][33];
    const int tx = threadIdx.x & 31;
    const int ty = threadIdx.x >> 5;   // 0..7
    int b = blockIdx.x;

    if (b < 2 * W1_TILES_PER_SET) {
        const int which = b >= W1_TILES_PER_SET;
        if (which) b -= W1_TILES_PER_SET;
        const int d0 = (b >> 3) * 32;
        const int h0 = (b & 7) * 32;
        const float* src = which ? i_w1 : u_w1;
        #pragma unroll
        for (int dy = 0; dy < 4; dy++) {
            int d = d0 + ty + dy * 8;
            tile[ty + dy * 8][tx] = src[(size_t)d * H_DIM + h0 + tx];
        }
        __syncthreads();
        #pragma unroll
        for (int dy = 0; dy < 4; dy++) {
            int h = h0 + ty + dy * 8;
            g_w1t[which][h][d0 + tx] = __float2half_rn(tile[tx][ty + dy * 8]);
        }
    } else {
        b -= 2 * W1_TILES_PER_SET;
        const int which = b >= W2_TILES_PER_SET;
        if (which) b -= W2_TILES_PER_SET;
        const int h0 = (b >> 1) * 32;
        const int o0 = (b & 1) * 32;
        const float* src = which ? i_w2 : u_w2;
        #pragma unroll
        for (int hy = 0; hy < 4; hy++) {
            int h = h0 + ty + hy * 8;
            tile[ty + hy * 8][tx] = src[(size_t)h * O_DIM + o0 + tx];
        }
        __syncthreads();
        #pragma unroll
        for (int oy = 0; oy < 4; oy++) {
            int o = o0 + ty + oy * 8;
            g_w2t[which][o][h0 + tx] = __float2half_rn(tile[tx][ty + oy * 8]);
        }
    }
}

// ---------------------------------------------------------------------------
// A-path helpers: LDG chunk -> fp32 regs; cvt+STS regs -> SW128 stage
// ---------------------------------------------------------------------------
__device__ __forceinline__ void ldg_A(const float* __restrict__ x, int m0, int c,
                                      int tid, float4 v[4]) {
    #pragma unroll
    for (int k = 0; k < 4; k++) {
        int u = tid + k * NTHREADS;          // 0..2047 float4 units
        int row = u >> 4, col4 = u & 15;
        v[k] = *((const float4*)(x + (size_t)(m0 + row) * D_IN + c * KC) + col4);
    }
}

__device__ __forceinline__ void sts_A(char* smem, uint32_t aoff, int tid, const float4 v[4]) {
    #pragma unroll
    for (int k = 0; k < 4; k++) {
        int u = tid + k * NTHREADS;
        int row = u >> 4, col4 = u & 15;
        __half2 h01 = __floats2half2_rn(v[k].x, v[k].y);
        __half2 h23 = __floats2half2_rn(v[k].z, v[k].w);
        uint2 pk;
        pk.x = *(uint32_t*)&h01;
        pk.y = *(uint32_t*)&h23;
        *(uint2*)(smem + aoff + SW128((uint32_t)(row * 128 + col4 * 8))) = pk;
    }
}

__device__ __forceinline__ void ld_B(uint32_t sb, uint32_t boff, const __half* __restrict__ w1,
                                     int c, int tid) {
    #pragma unroll
    for (int k = 0; k < 4; k++) {
        int g = tid + k * NTHREADS;          // 0..2047 16B granules
        int h = g >> 3, gg = g & 7;
        CP_ASYNC_16(sb + boff + SW128((uint32_t)(h * 128 + gg * 16)),
                    w1 + (size_t)h * D_IN + c * KC + gg * 8);
    }
}

// One ks-block of layer-1 with CROSS-KS pipelining: fragments for (ks, ng+1)
// — and at ng==3, for (ks+1, 0) including both A fragments — are loaded
// BEFORE the 4 MMAs of the current step, so every LDSM after the chunk's
// first three has ≥4 MMAs (~32cyc) of tensor back-pressure covering it.
// a[2][2][4] is double-buffered on ks&1; b[2][4] alternates per (ks*4+ng)&1.
// sa/sbb are pre-swizzled per-thread bases (R11 identity).
__device__ __forceinline__ void compute_ks_pipe(uint32_t ah, uint32_t bt, int ks,
                                                uint32_t sa, uint32_t sbb,
                                                uint32_t a[2][2][4], uint32_t b[2][4],
                                                float cacc[2][8][4]) {
    const uint32_t skb = sbb ^ (uint32_t)(ks * 32);
    const int ab = ks & 1;
    #pragma unroll
    for (int ng = 0; ng < 4; ng++) {
        const int cur = (ks * 4 + ng) & 1;
        const int nxt = cur ^ 1;
        if (ng < 3) {
            ldsm_x4(bt + skb + (uint32_t)((ng + 1) * 2048), b[nxt]);
        } else if (ks < 3) {
            const uint32_t knb = (uint32_t)((ks + 1) * 32);
            ldsm_x4(bt + (sbb ^ knb), b[nxt]);
            ldsm_x4(ah + (sa ^ knb),        a[ab ^ 1][0]);
            ldsm_x4(ah + (sa ^ knb) + 2048, a[ab ^ 1][1]);
        }
        mma16816(cacc[0][ng * 2 + 0], a[ab][0], b[cur][0], b[cur][1]);
        mma16816(cacc[1][ng * 2 + 0], a[ab][1], b[cur][0], b[cur][1]);
        mma16816(cacc[0][ng * 2 + 1], a[ab][0], b[cur][2], b[cur][3]);
        mma16816(cacc[1][ng * 2 + 1], a[ab][1], b[cur][2], b[cur][3]);
    }
}

// ---------------------------------------------------------------------------
// Main fused kernel: 512 threads, 16 warps (4M x 4N), M-tile 128
// ---------------------------------------------------------------------------
__global__ void __launch_bounds__(NTHREADS, 1)
llama_head_kernel(const float* __restrict__ user_emb,
                  const float* __restrict__ item_emb,
                  const float* __restrict__ u_b1, const float* __restrict__ i_b1,
                  const float* __restrict__ u_b2, const float* __restrict__ i_b2,
                  float* __restrict__ out) {
    extern __shared__ __align__(1024) char smem[];
    const uint32_t sb = smem_u32(smem);

    const int tid  = threadIdx.x;
    const int lane = tid & 31;
    const int wid  = tid >> 5;
    const int wm   = wid >> 2;          // 0..3  (M groups of 32 rows)
    const int wn   = wid & 3;           // 0..3  (N groups of 64 cols)
    const int m0   = blockIdx.x * TILE_M;
    const int lt   = lane >> 3;         // ldmatrix tile index 0..3
    const int lr   = lane & 7;          // ldmatrix row-in-tile
    const int qr   = lane >> 2;         // mma row within m8 group
    const int qc   = 2 * (lane & 3);    // mma col pair base

    const uint32_t a_row_base = (uint32_t)((wm * 32 + (lt & 1) * 8 + lr) * 128 + (lt >> 1) * 16);
    const uint32_t b_row_base = (uint32_t)((wn * 64 + (lt >> 1) * 8 + lr) * 128 + (lt & 1) * 16);
    const uint32_t sa  = SW128(a_row_base);   // pre-swizzled LDSM bases
    const uint32_t sbb = SW128(b_row_base);

    // ---- init: biases, dot buffer ----
    if (tid < 256) ((float*)(smem + OFF_B1))[tid] = u_b1[tid];
    else           ((float*)(smem + OFF_B1))[tid] = i_b1[tid - 256];
    if (tid < 64)        ((float*)(smem + OFF_B2))[tid] = u_b2[tid];
    else if (tid < 128)  ((float*)(smem + OFF_B2))[tid] = i_b2[tid - 64];
    if (tid < 128) ((float*)(smem + OFF_DOT))[tid] = 0.0f;

    for (int p = 0; p < 2; p++) {
        const float*  x  = p ? item_emb : user_emb;
        const __half* w1 = &g_w1t[p][0][0];
        const __half* w2 = &g_w2t[p][0][0];

        float cacc[2][8][4];
        #pragma unroll
        for (int i = 0; i < 2; i++)
            #pragma unroll
            for (int j = 0; j < 8; j++)
                #pragma unroll
                for (int q = 0; q < 4; q++) cacc[i][j][q] = 0.0f;

        // ---- prologue ----
        float4 rA[4];
        {
            ldg_A(x, m0, 0, tid, rA);
            sts_A(smem, OFF_A(0), tid, rA);
            // B chunk 0 + THIS phase's w2 tiles (w2 reloaded every phase —
            // single OFF_W2 buffer; phase 1 needs i_w2).
            ld_B(sb, OFF_B(0), w1, 0, tid);
            #pragma unroll
            for (int k = 0; k < 4; k++) {
                int g  = tid + k * NTHREADS;      // 0..2047
                int hc = g >> 9;
                int rr = g & 511;
                int o  = rr >> 3;
                int gg = rr & 7;
                const __half* src = w2 + (size_t)o * H_DIM + hc * KC + gg * 8;
                uint32_t dst = sb + OFF_W2 + hc * 8192 + SW128((uint32_t)(o * 128 + gg * 16));
                CP_ASYNC_16(dst, src);
            }
            CP_ASYNC_COMMIT();
            ldg_A(x, m0, 1, tid, rA);   // chunk 1 -> regs, consumed next iter
        }

        // ====== layer-1 mainloop: cross-ks pipelined compute ======
        for (int c = 0; c < NCHUNK; c++) {
            const int s  = c & 1;
            const int sn = s ^ 1;

            CP_ASYNC_WAIT_ALL();     // my B(c) (and W2 on first iter) complete
            __syncthreads();         // all threads' B(c) visible; compute(c-1) done

            const uint32_t ah = sb + OFF_A(s);
            const uint32_t bt = sb + OFF_B(s);
            const bool refill = (c + 1 < NCHUNK);

            // chunk-top preload: the only 3 exposed LDSMs per chunk
            uint32_t a[2][2][4];
            uint32_t b[2][4];
            ldsm_x4(ah + sa,        a[0][0]);
            ldsm_x4(ah + sa + 2048, a[0][1]);
            ldsm_x4(bt + sbb,       b[0]);

            compute_ks_pipe(ah, bt, 0, sa, sbb, a, b, cacc);
            if (refill) sts_A(smem, OFF_A(sn), tid, rA);        // A(c+1) regs->smem
            compute_ks_pipe(ah, bt, 1, sa, sbb, a, b, cacc);
            if (refill) {
                ld_B(sb, OFF_B(sn), w1, c + 1, tid);            // B(c+1) via cp.async
                CP_ASYNC_COMMIT();
            }
            compute_ks_pipe(ah, bt, 2, sa, sbb, a, b, cacc);
            if (c + 2 < NCHUNK) ldg_A(x, m0, c + 2, tid, rA);   // A(c+2) -> regs
            compute_ks_pipe(ah, bt, 3, sa, sbb, a, b, cacc);
        }
        __syncthreads();   // all warps done reading stages before H overwrites them

        // ============ layer-1 epilogue: bias + relu + fp16 h tiles ============
        {
            const float* b1s = (const float*)(smem + OFF_B1 + p * 1024);
            #pragma unroll
            for (int mi = 0; mi < 2; mi++) {
                const int r0 = wm * 32 + mi * 16 + qr;
                #pragma unroll
                for (int g = 0; g < 8; g++) {
                    const int nc = wn * 64 + g * 8 + qc;
                    float bb0 = b1s[nc], bb1 = b1s[nc + 1];
                    float v00 = fmaxf(cacc[mi][g][0] + bb0, 0.0f);
                    float v01 = fmaxf(cacc[mi][g][1] + bb1, 0.0f);
                    float v10 = fmaxf(cacc[mi][g][2] + bb0, 0.0f);
                    float v11 = fmaxf(cacc[mi][g][3] + bb1, 0.0f);
                    __half2 hv0 = __floats2half2_rn(v00, v01);
                    __half2 hv1 = __floats2half2_rn(v10, v11);
                    const int hc = nc >> 6, colc = nc & 63;
                    *(uint32_t*)(smem + OFF_H(hc) + SW128((uint32_t)(r0 * 128 + colc * 2)))
                        = *(uint32_t*)&hv0;
                    *(uint32_t*)(smem + OFF_H(hc) + SW128((uint32_t)((r0 + 8) * 128 + colc * 2)))
                        = *(uint32_t*)&hv1;
                }
            }
        }
        __syncthreads();

        // ===================== layer-2: [128,64] = h[128,256] x w2t ===========
        float c2[2][2][4];
        #pragma unroll
        for (int i = 0; i < 2; i++)
            #pragma unroll
            for (int j = 0; j < 2; j++)
                #pragma unroll
                for (int q = 0; q < 4; q++) c2[i][j][q] = 0.0f;

        #pragma unroll
        for (int ks = 0; ks < 16; ks++) {
            const int hc = ks >> 2, k0 = (ks & 3) * 16;
            uint32_t a[2][4], b[4];
            #pragma unroll
            for (int mi = 0; mi < 2; mi++) {
                uint32_t aoff = SW128((uint32_t)(
                    (wm * 32 + mi * 16 + (lt & 1) * 8 + lr) * 128 +
                    (k0 + (lt >> 1) * 8) * 2));
                ldsm_x4(sb + OFF_H(hc) + aoff, a[mi]);
            }
            uint32_t boff = SW128((uint32_t)(
                (wn * 16 + (lt >> 1) * 8 + lr) * 128 + (k0 + (lt & 1) * 8) * 2));
            ldsm_x4(sb + OFF_W2 + hc * 8192 + boff, b);
            #pragma unroll
            for (int mi = 0; mi < 2; mi++) {
                mma16816(c2[mi][0], a[mi], b[0], b[1]);
                mma16816(c2[mi][1], a[mi], b[2], b[3]);
            }
        }

        // ===================== layer-2 epilogue ===============================
        if (p == 0) {
            const float* b2s = (const float*)(smem + OFF_B2);
            float* u2 = (float*)(smem + OFF_U2);
            #pragma unroll
            for (int mi = 0; mi < 2; mi++) {
                const int r0 = wm * 32 + mi * 16 + qr;
                #pragma unroll
                for (int g = 0; g < 2; g++) {
                    const int n = wn * 16 + g * 8 + qc;
                    u2[r0 * 64 + n]           = c2[mi][g][0] + b2s[n];
                    u2[r0 * 64 + n + 1]       = c2[mi][g][1] + b2s[n + 1];
                    u2[(r0 + 8) * 64 + n]     = c2[mi][g][2] + b2s[n];
                    u2[(r0 + 8) * 64 + n + 1] = c2[mi][g][3] + b2s[n + 1];
                }
            }
            __syncthreads();   // u2 complete; all H/W2 reads done before phase-1 refills
        } else {
            const float* b2s = (const float*)(smem + OFF_B2 + 256);
            const float* u2 = (const float*)(smem + OFF_U2);
            float* dotb = (float*)(smem + OFF_DOT);
            #pragma unroll
            for (int mi = 0; mi < 2; mi++) {
                const int r0 = wm * 32 + mi * 16 + qr;
                float pr0 = 0.0f, pr1 = 0.0f;
                #pragma unroll
                for (int g = 0; g < 2; g++) {
                    const int n = wn * 16 + g * 8 + qc;
                    float bv0 = b2s[n], bv1 = b2s[n + 1];
                    pr0 += (c2[mi][g][0] + bv0) * u2[r0 * 64 + n];
                    pr0 += (c2[mi][g][1] + bv1) * u2[r0 * 64 + n + 1];
                    pr1 += (c2[mi][g][2] + bv0) * u2[(r0 + 8) * 64 + n];
                    pr1 += (c2[mi][g][3] + bv1) * u2[(r0 + 8) * 64 + n + 1];
                }
                pr0 += __shfl_xor_sync(0xFFFFFFFF, pr0, 1);
                pr0 += __shfl_xor_sync(0xFFFFFFFF, pr0, 2);
                pr1 += __shfl_xor_sync(0xFFFFFFFF, pr1, 1);
                pr1 += __shfl_xor_sync(0xFFFFFFFF, pr1, 2);
                if ((lane & 3) == 0) {
                    atomicAdd(&dotb[r0], pr0);
                    atomicAdd(&dotb[r0 + 8], pr1);
                }
            }
            __syncthreads();
        }
    }

    // ===================== final: sigmoid(dot) =====================
    if (tid < 128) {
        float d = ((const float*)(smem + OFF_DOT))[tid];
        out[m0 + tid] = 1.0f / (1.0f + expf(-d));
    }
}

// ---------------------------------------------------------------------------
// kernel_launch
// ---------------------------------------------------------------------------
extern "C" void kernel_launch(void* const* d_in, const int* in_sizes, int n_in,
                              void* d_out, int out_size) {
    const float* user_emb = (const float*)d_in[0];
    const float* item_emb = (const float*)d_in[1];
    const float* u_w1 = (const float*)d_in[2];
    const float* u_b1 = (const float*)d_in[3];
    const float* u_w2 = (const float*)d_in[4];
    const float* u_b2 = (const float*)d_in[5];
    const float* i_w1 = (const float*)d_in[6];
    const float* i_b1 = (const float*)d_in[7];
    const float* i_w2 = (const float*)d_in[8];
    const float* i_b2 = (const float*)d_in[9];
    float* out = (float*)d_out;

    cudaFuncSetAttribute(llama_head_kernel,
                         cudaFuncAttributeMaxDynamicSharedMemorySize, SMEM_BYTES);

    const int prep_blocks = 2 * W1_TILES_PER_SET + 2 * W2_TILES_PER_SET;
    prep_weights_kernel<<<prep_blocks, 256>>>(u_w1, i_w1, u_w2, i_w2);

    llama_head_kernel<<<NROWS / TILE_M, NTHREADS, SMEM_BYTES>>>(
        user_emb, item_emb, u_b1, i_b1, u_b2, i_b2, out);
}